// round 7
// baseline (speedup 1.0000x reference)
#include <cuda_runtime.h>

// ---------------------------------------------------------------------------
// M1_17008070492428: batched tiny Hopfield attention + classifier head.
//   B=131072 samples, each (S=14, D=16) -> (7,) softmax probs.
// R6: occupancy push. One sample per warp-iteration (halves live registers),
//     __launch_bounds__(128,6) -> regs<=85 -> 24 warps/SM (was 14).
// Pipeline (unchanged): PI-permuted QKV weights make each MMA C-fragment
// coincide with the next MMA's A/B fragment layout; Q,K,P in registers;
// V transposed through one 16x24 smem tile per warp; raw f32 bits fed to
// tf32 MMAs (truncation, no cvt).
// ---------------------------------------------------------------------------

typedef unsigned int u32;
#define LN_EPS 1e-5f
#define FULLM 0xffffffffu

__device__ __forceinline__ u32 f2t(float x) {          // f32 bits as tf32
    return __float_as_uint(x);
}
__device__ __forceinline__ void mma8(float& d0, float& d1, float& d2, float& d3,
                                     u32 a0, u32 a1, u32 a2, u32 a3,
                                     u32 b0, u32 b1,
                                     float c0, float c1, float c2, float c3) {
    asm("mma.sync.aligned.m16n8k8.row.col.f32.tf32.tf32.f32 "
        "{%0,%1,%2,%3},{%4,%5,%6,%7},{%8,%9},{%10,%11,%12,%13};"
        : "=f"(d0), "=f"(d1), "=f"(d2), "=f"(d3)
        : "r"(a0), "r"(a1), "r"(a2), "r"(a3), "r"(b0), "r"(b1),
          "f"(c0), "f"(c1), "f"(c2), "f"(c3));
}

struct __align__(16) Params {
    float wq[16][16], wk[16][16], wv[16][16];  // PI-permuted rows, LN-gamma folded
    float bq[16], bk[16], bv[16];              // PI-permuted, LN-beta folded
    float M[7][16];                            // Wb @ Wo (true-d columns)
    float ez[8];
    float wm[16];                              // Wm padded with zeros
};
__device__ Params g_P;

__global__ void setup_kernel(
    const float* __restrict__ lnqg, const float* __restrict__ lnqb,
    const float* __restrict__ lnkg, const float* __restrict__ lnkb,
    const float* __restrict__ lnvg, const float* __restrict__ lnvb,
    const float* __restrict__ Wq,  const float* __restrict__ bq,
    const float* __restrict__ Wk,  const float* __restrict__ bk,
    const float* __restrict__ Wv,  const float* __restrict__ bv,
    const float* __restrict__ Wo,  const float* __restrict__ bo,
    const float* __restrict__ Wm,  const float* __restrict__ bm,
    const float* __restrict__ Wb,  const float* __restrict__ bb)
{
    const int PI[16] = {0,4,1,5,2,6,3,7, 8,12,9,13,10,14,11,15};
    const int t = threadIdx.x;           // 256 threads, 1 block
    const int e = t >> 4, d = t & 15;
    const int pe = PI[e];
    g_P.wq[e][d] = Wq[pe * 16 + d] * lnqg[d];
    g_P.wk[e][d] = Wk[pe * 16 + d] * lnkg[d];
    g_P.wv[e][d] = Wv[pe * 16 + d] * lnvg[d];
    if (t < 16) {
        const int p = PI[t];
        float aq = bq[p], ak = bk[p], av = bv[p];
        #pragma unroll
        for (int i = 0; i < 16; i++) {
            aq = fmaf(lnqb[i], Wq[p * 16 + i], aq);
            ak = fmaf(lnkb[i], Wk[p * 16 + i], ak);
            av = fmaf(lnvb[i], Wv[p * 16 + i], av);
        }
        g_P.bq[t] = aq; g_P.bk[t] = ak; g_P.bv[t] = av;
        g_P.wm[t] = (t < 14) ? Wm[t] : 0.f;
    }
    if (t < 112) {
        const int c = t >> 4, dd = t & 15;
        float s = 0.f;
        for (int o = 0; o < 128; o++)
            s = fmaf(Wb[c * 128 + o], Wo[o * 16 + dd], s);
        g_P.M[c][dd] = s;
    }
    if (t >= 112 && t < 119) {
        const int c = t - 112;
        float c0 = 0.f;
        for (int s = 0; s < 14; s++) c0 += Wm[s];
        float z = bb[c];
        const float bmv = bm[0];
        for (int o = 0; o < 128; o++)
            z = fmaf(Wb[c * 128 + o], fmaf(c0, bo[o], bmv), z);
        g_P.ez[c] = z;
    }
    if (t == 119) g_P.ez[7] = 0.f;
}

__global__ __launch_bounds__(128, 6) void hopfield_kernel(
    const float* __restrict__ x, float* __restrict__ out, int nB)
{
    __shared__ __align__(16) float smVt[4][16 * 24];   // 6 KB: one tile/warp
    const int tid  = threadIdx.x;
    const int lane = tid & 31;
    const int wid  = tid >> 5;
    const int fg   = lane >> 2;     // 0..7  (row group / B n-col)
    const int tg   = lane & 3;      // 0..3  (thread-in-quad)
    float* Vt = smVt[wid];

    // ---- persistent weight B-fragments (raw f32 = truncated tf32) ----
    u32   bw[3][2][2][2];           // [proj][ntile][kstep][reg]
    float bs[3][2][2];
    {
        const float* Wp[3] = { &g_P.wq[0][0], &g_P.wk[0][0], &g_P.wv[0][0] };
        const float* Bp[3] = { g_P.bq, g_P.bk, g_P.bv };
        #pragma unroll
        for (int p = 0; p < 3; p++) {
            #pragma unroll
            for (int nt = 0; nt < 2; nt++) {
                #pragma unroll
                for (int ks = 0; ks < 2; ks++) {
                    const float* base = Wp[p] + (fg + 8 * nt) * 16 + 8 * ks;
                    bw[p][nt][ks][0] = f2t(__ldg(base + tg));
                    bw[p][nt][ks][1] = f2t(__ldg(base + tg + 4));
                }
                bs[p][nt][0] = __ldg(Bp[p] + 2 * tg + 8 * nt);
                bs[p][nt][1] = __ldg(Bp[p] + 2 * tg + 8 * nt + 1);
            }
        }
    }
    const float wmLo = g_P.wm[fg];
    const float wmHi = g_P.wm[fg + 8];      // 0 for rows 14,15
    float4 mz = make_float4(0.f, 0.f, 0.f, 0.f);
    float ezv = 0.f;
    if (fg < 7) {
        float2 a = *(const float2*)&g_P.M[fg][2 * tg];
        float2 b = *(const float2*)&g_P.M[fg][8 + 2 * tg];
        mz = make_float4(a.x, a.y, b.x, b.y);
        ezv = g_P.ez[fg];
    }

    const int totalWarps = gridDim.x * 4;
    for (int samp = blockIdx.x * 4 + wid; samp < nB; samp += totalWarps) {
        const float* xs = x + (long long)samp * 224;

        // ---- load x directly in fragment layout + LN via quad shuffles ----
        float xlo[4], xhi[4];
        #pragma unroll
        for (int u = 0; u < 4; u++) {
            xlo[u] = __ldg(xs + fg * 16 + tg + 4 * u);
            xhi[u] = (fg < 6) ? __ldg(xs + (fg + 8) * 16 + tg + 4 * u) : 0.f;
        }
        float s1l = ((xlo[0] + xlo[1]) + (xlo[2] + xlo[3]));
        float s2l = xlo[0] * xlo[0];
        s2l = fmaf(xlo[1], xlo[1], s2l); s2l = fmaf(xlo[2], xlo[2], s2l); s2l = fmaf(xlo[3], xlo[3], s2l);
        float s1h = ((xhi[0] + xhi[1]) + (xhi[2] + xhi[3]));
        float s2h = xhi[0] * xhi[0];
        s2h = fmaf(xhi[1], xhi[1], s2h); s2h = fmaf(xhi[2], xhi[2], s2h); s2h = fmaf(xhi[3], xhi[3], s2h);
        s1l += __shfl_xor_sync(FULLM, s1l, 1); s1l += __shfl_xor_sync(FULLM, s1l, 2);
        s2l += __shfl_xor_sync(FULLM, s2l, 1); s2l += __shfl_xor_sync(FULLM, s2l, 2);
        s1h += __shfl_xor_sync(FULLM, s1h, 1); s1h += __shfl_xor_sync(FULLM, s1h, 2);
        s2h += __shfl_xor_sync(FULLM, s2h, 1); s2h += __shfl_xor_sync(FULLM, s2h, 2);
        const float mL = s1l * 0.0625f;
        const float rL = rsqrtf(fmaf(-mL, mL, s2l * 0.0625f) + LN_EPS);
        const float mH = s1h * 0.0625f;
        const float rH = rsqrtf(fmaf(-mH, mH, s2h * 0.0625f) + LN_EPS);
        u32 a0 = f2t((xlo[0] - mL) * rL), a1 = f2t((xhi[0] - mH) * rH);
        u32 a2 = f2t((xlo[1] - mL) * rL), a3 = f2t((xhi[1] - mH) * rH);
        u32 a4 = f2t((xlo[2] - mL) * rL), a5 = f2t((xhi[2] - mH) * rH);
        u32 a6 = f2t((xlo[3] - mL) * rL), a7 = f2t((xhi[3] - mH) * rH);

        // ---- QKV (PI-permuted): C-frags land in true-d layout ----
        float Q[8], K[8], V[8];
        #pragma unroll
        for (int p = 0; p < 3; p++) {
            float* D = (p == 0) ? Q : ((p == 1) ? K : V);
            #pragma unroll
            for (int nt = 0; nt < 2; nt++) {
                float d0, d1, d2, d3;
                mma8(d0, d1, d2, d3, a0, a1, a2, a3,
                     bw[p][nt][0][0], bw[p][nt][0][1],
                     bs[p][nt][0], bs[p][nt][1], bs[p][nt][0], bs[p][nt][1]);
                mma8(d0, d1, d2, d3, a4, a5, a6, a7,
                     bw[p][nt][1][0], bw[p][nt][1][1], d0, d1, d2, d3);
                D[nt * 4 + 0] = d0; D[nt * 4 + 1] = d1;
                D[nt * 4 + 2] = d2; D[nt * 4 + 3] = d3;
            }
        }

        // ---- stage V transposed: Vt[d][key], stride 24 (conflict-free) ----
        __syncwarp();                      // prior iteration's reads done
        Vt[ tg       * 24 + fg    ] = V[0];
        Vt[(tg + 4)  * 24 + fg    ] = V[1];
        Vt[ tg       * 24 + fg + 8] = V[2];
        Vt[(tg + 4)  * 24 + fg + 8] = V[3];
        Vt[(tg + 8)  * 24 + fg    ] = V[4];
        Vt[(tg + 12) * 24 + fg    ] = V[5];
        Vt[(tg + 8)  * 24 + fg + 8] = V[6];
        Vt[(tg + 12) * 24 + fg + 8] = V[7];

        // ---- S = Q K^T : pure register MMA ----
        u32 qa0 = f2t(Q[0]), qa1 = f2t(Q[2]), qa2 = f2t(Q[1]), qa3 = f2t(Q[3]);
        u32 qa4 = f2t(Q[4]), qa5 = f2t(Q[6]), qa6 = f2t(Q[5]), qa7 = f2t(Q[7]);
        float t0, t1, t2, t3, u0, u1, u2, u3;
        mma8(t0, t1, t2, t3, qa0, qa1, qa2, qa3, f2t(K[0]), f2t(K[1]), 0.f, 0.f, 0.f, 0.f);
        mma8(t0, t1, t2, t3, qa4, qa5, qa6, qa7, f2t(K[4]), f2t(K[5]), t0, t1, t2, t3);
        mma8(u0, u1, u2, u3, qa0, qa1, qa2, qa3, f2t(K[2]), f2t(K[3]), 0.f, 0.f, 0.f, 0.f);
        mma8(u0, u1, u2, u3, qa4, qa5, qa6, qa7, f2t(K[6]), f2t(K[7]), u0, u1, u2, u3);
        if (tg == 3) { u0 = -1e30f; u1 = -1e30f; u2 = -1e30f; u3 = -1e30f; }  // keys 14,15

        // ---- softmax rows (quad shuffles), fold wm*inv into P ----
        float mLo = fmaxf(fmaxf(t0, t1), fmaxf(u0, u1));
        mLo = fmaxf(mLo, __shfl_xor_sync(FULLM, mLo, 1));
        mLo = fmaxf(mLo, __shfl_xor_sync(FULLM, mLo, 2));
        float mHi = fmaxf(fmaxf(t2, t3), fmaxf(u2, u3));
        mHi = fmaxf(mHi, __shfl_xor_sync(FULLM, mHi, 1));
        mHi = fmaxf(mHi, __shfl_xor_sync(FULLM, mHi, 2));
        float e0 = __expf(t0 - mLo), e1 = __expf(t1 - mLo), e4 = __expf(u0 - mLo), e5 = __expf(u1 - mLo);
        float e2 = __expf(t2 - mHi), e3 = __expf(t3 - mHi), e6 = __expf(u2 - mHi), e7 = __expf(u3 - mHi);
        float sl = (e0 + e1) + (e4 + e5);
        sl += __shfl_xor_sync(FULLM, sl, 1); sl += __shfl_xor_sync(FULLM, sl, 2);
        float sh = (e2 + e3) + (e6 + e7);
        sh += __shfl_xor_sync(FULLM, sh, 1); sh += __shfl_xor_sync(FULLM, sh, 2);
        const float wl = wmLo * __fdividef(1.f, sl);
        const float wh = wmHi * __fdividef(1.f, sh);
        u32 pa0 = f2t(e0 * wl), pa1 = f2t(e2 * wh), pa2 = f2t(e1 * wl), pa3 = f2t(e3 * wh);
        u32 pb0 = f2t(e4 * wl), pb1 = f2t(e6 * wh), pb2 = f2t(e5 * wl), pb3 = f2t(e7 * wh);

        __syncwarp();
        const float2 v00 = *(const float2*)&Vt[fg * 24 + 2 * tg];
        const float2 v01 = *(const float2*)&Vt[fg * 24 + 8 + 2 * tg];
        const float2 v10 = *(const float2*)&Vt[(fg + 8) * 24 + 2 * tg];
        const float2 v11 = *(const float2*)&Vt[(fg + 8) * 24 + 8 + 2 * tg];

        // ---- O = P' V (key dim permuted consistently on both sides) ----
        float o0, o1, o2, o3, p0, p1, p2, p3;
        mma8(o0, o1, o2, o3, pa0, pa1, pa2, pa3, f2t(v00.x), f2t(v00.y), 0.f, 0.f, 0.f, 0.f);
        mma8(o0, o1, o2, o3, pb0, pb1, pb2, pb3, f2t(v01.x), f2t(v01.y), o0, o1, o2, o3);
        mma8(p0, p1, p2, p3, pa0, pa1, pa2, pa3, f2t(v10.x), f2t(v10.y), 0.f, 0.f, 0.f, 0.f);
        mma8(p0, p1, p2, p3, pb0, pb1, pb2, pb3, f2t(v11.x), f2t(v11.y), p0, p1, p2, p3);

        // ---- t[d]: column sums over q (rows already weighted) ----
        float c0 = o0 + o2, c1 = o1 + o3, c2 = p0 + p2, c3 = p1 + p3;
        #pragma unroll
        for (int off = 4; off <= 16; off <<= 1) {
            c0 += __shfl_xor_sync(FULLM, c0, off);
            c1 += __shfl_xor_sync(FULLM, c1, off);
            c2 += __shfl_xor_sync(FULLM, c2, off);
            c3 += __shfl_xor_sync(FULLM, c3, off);
        }

        // ---- z[c] per fg-group (partial dot; ez added ONCE after quad sum) ----
        float z = (fg < 7)
            ? fmaf(mz.x, c0, fmaf(mz.y, c1, fmaf(mz.z, c2, mz.w * c3)))
            : 0.f;
        z += __shfl_xor_sync(FULLM, z, 1);
        z += __shfl_xor_sync(FULLM, z, 2);
        float zq = (fg < 7) ? (z + ezv) : -1e30f;
        float zm = zq;
        zm = fmaxf(zm, __shfl_xor_sync(FULLM, zm, 4));
        zm = fmaxf(zm, __shfl_xor_sync(FULLM, zm, 8));
        zm = fmaxf(zm, __shfl_xor_sync(FULLM, zm, 16));
        float ex = __expf(zq - zm);
        float se = ex;
        se += __shfl_xor_sync(FULLM, se, 4);
        se += __shfl_xor_sync(FULLM, se, 8);
        se += __shfl_xor_sync(FULLM, se, 16);
        if (tg == 0 && fg < 7)
            out[samp * 7 + fg] = __fdividef(ex, se);
    }
}

extern "C" void kernel_launch(void* const* d_in, const int* in_sizes, int n_in,
                              void* d_out, int out_size)
{
    const float* sample = (const float*)d_in[0];
    setup_kernel<<<1, 256>>>(
        (const float*)d_in[1],  (const float*)d_in[2],
        (const float*)d_in[3],  (const float*)d_in[4],
        (const float*)d_in[5],  (const float*)d_in[6],
        (const float*)d_in[7],  (const float*)d_in[8],
        (const float*)d_in[9],  (const float*)d_in[10],
        (const float*)d_in[11], (const float*)d_in[12],
        (const float*)d_in[13], (const float*)d_in[14],
        (const float*)d_in[15], (const float*)d_in[16],
        (const float*)d_in[17], (const float*)d_in[18]);

    const int nB = in_sizes[0] / 224;   // B = 131072
    hopfield_kernel<<<2048, 128>>>(sample, (float*)d_out, nB);
}

// round 8
// speedup vs baseline: 1.0995x; 1.0995x over previous
#include <cuda_runtime.h>

// ---------------------------------------------------------------------------
// M1_17008070492428: batched tiny Hopfield attention + classifier head.
//   B=131072 samples, each (S=14, D=16) -> (7,) softmax probs.
// R7 = R5 (2-sample unroll, launch_bounds(128,4)) + coalesced input path:
//   x loaded as contiguous LDG.128, staged to smem at stride 20
//   (bank-perfect for the fragment gather), then 8 conflict-free LDS.32
//   per lane. Replaces the 8 scattered LDG.32 (~64 L1 wavefronts/sample).
// Pipeline: PI-permuted QKV weights make each MMA C-fragment coincide with
// the next MMA's A/B fragment layout; Q,K,P in registers; V transposed
// through the same smem tile (stride 24); raw f32 bits fed to tf32 MMAs.
// ---------------------------------------------------------------------------

typedef unsigned int u32;
#define LN_EPS 1e-5f
#define FULLM 0xffffffffu

__device__ __forceinline__ u32 f2t(float x) {          // f32 bits as tf32
    return __float_as_uint(x);
}
__device__ __forceinline__ void mma8(float& d0, float& d1, float& d2, float& d3,
                                     u32 a0, u32 a1, u32 a2, u32 a3,
                                     u32 b0, u32 b1,
                                     float c0, float c1, float c2, float c3) {
    asm("mma.sync.aligned.m16n8k8.row.col.f32.tf32.tf32.f32 "
        "{%0,%1,%2,%3},{%4,%5,%6,%7},{%8,%9},{%10,%11,%12,%13};"
        : "=f"(d0), "=f"(d1), "=f"(d2), "=f"(d3)
        : "r"(a0), "r"(a1), "r"(a2), "r"(a3), "r"(b0), "r"(b1),
          "f"(c0), "f"(c1), "f"(c2), "f"(c3));
}

struct __align__(16) Params {
    float wq[16][16], wk[16][16], wv[16][16];  // PI-permuted rows, LN-gamma folded
    float bq[16], bk[16], bv[16];              // PI-permuted, LN-beta folded
    float M[7][16];                            // Wb @ Wo (true-d columns)
    float ez[8];
    float wm[16];                              // Wm padded with zeros
};
__device__ Params g_P;

__global__ void setup_kernel(
    const float* __restrict__ lnqg, const float* __restrict__ lnqb,
    const float* __restrict__ lnkg, const float* __restrict__ lnkb,
    const float* __restrict__ lnvg, const float* __restrict__ lnvb,
    const float* __restrict__ Wq,  const float* __restrict__ bq,
    const float* __restrict__ Wk,  const float* __restrict__ bk,
    const float* __restrict__ Wv,  const float* __restrict__ bv,
    const float* __restrict__ Wo,  const float* __restrict__ bo,
    const float* __restrict__ Wm,  const float* __restrict__ bm,
    const float* __restrict__ Wb,  const float* __restrict__ bb)
{
    const int PI[16] = {0,4,1,5,2,6,3,7, 8,12,9,13,10,14,11,15};
    const int t = threadIdx.x;           // 256 threads, 1 block
    const int e = t >> 4, d = t & 15;
    const int pe = PI[e];
    g_P.wq[e][d] = Wq[pe * 16 + d] * lnqg[d];
    g_P.wk[e][d] = Wk[pe * 16 + d] * lnkg[d];
    g_P.wv[e][d] = Wv[pe * 16 + d] * lnvg[d];
    if (t < 16) {
        const int p = PI[t];
        float aq = bq[p], ak = bk[p], av = bv[p];
        #pragma unroll
        for (int i = 0; i < 16; i++) {
            aq = fmaf(lnqb[i], Wq[p * 16 + i], aq);
            ak = fmaf(lnkb[i], Wk[p * 16 + i], ak);
            av = fmaf(lnvb[i], Wv[p * 16 + i], av);
        }
        g_P.bq[t] = aq; g_P.bk[t] = ak; g_P.bv[t] = av;
        g_P.wm[t] = (t < 14) ? Wm[t] : 0.f;
    }
    if (t < 112) {
        const int c = t >> 4, dd = t & 15;
        float s = 0.f;
        for (int o = 0; o < 128; o++)
            s = fmaf(Wb[c * 128 + o], Wo[o * 16 + dd], s);
        g_P.M[c][dd] = s;
    }
    if (t >= 112 && t < 119) {
        const int c = t - 112;
        float c0 = 0.f;
        for (int s = 0; s < 14; s++) c0 += Wm[s];
        float z = bb[c];
        const float bmv = bm[0];
        for (int o = 0; o < 128; o++)
            z = fmaf(Wb[c * 128 + o], fmaf(c0, bo[o], bmv), z);
        g_P.ez[c] = z;
    }
    if (t == 119) g_P.ez[7] = 0.f;
}

__global__ __launch_bounds__(128, 4) void hopfield_kernel(
    const float* __restrict__ x, float* __restrict__ out, int nB)
{
    __shared__ __align__(16) float smT[4][2][16 * 24];   // 12 KB: stage + Vt
    const int tid  = threadIdx.x;
    const int lane = tid & 31;
    const int wid  = tid >> 5;
    const int fg   = lane >> 2;     // 0..7  (row group / B n-col)
    const int tg   = lane & 3;      // 0..3  (thread-in-quad)

    // ---- persistent weight B-fragments (raw f32 = truncated tf32) ----
    u32   bw[3][2][2][2];           // [proj][ntile][kstep][reg]
    float bs[3][2][2];
    {
        const float* Wp[3] = { &g_P.wq[0][0], &g_P.wk[0][0], &g_P.wv[0][0] };
        const float* Bp[3] = { g_P.bq, g_P.bk, g_P.bv };
        #pragma unroll
        for (int p = 0; p < 3; p++) {
            #pragma unroll
            for (int nt = 0; nt < 2; nt++) {
                #pragma unroll
                for (int ks = 0; ks < 2; ks++) {
                    const float* base = Wp[p] + (fg + 8 * nt) * 16 + 8 * ks;
                    bw[p][nt][ks][0] = f2t(__ldg(base + tg));
                    bw[p][nt][ks][1] = f2t(__ldg(base + tg + 4));
                }
                bs[p][nt][0] = __ldg(Bp[p] + 2 * tg + 8 * nt);
                bs[p][nt][1] = __ldg(Bp[p] + 2 * tg + 8 * nt + 1);
            }
        }
    }
    const float wmLo = g_P.wm[fg];
    const float wmHi = g_P.wm[fg + 8];      // 0 for rows 14,15
    float4 mz = make_float4(0.f, 0.f, 0.f, 0.f);
    float ezv = 0.f;
    if (fg < 7) {
        float2 a = *(const float2*)&g_P.M[fg][2 * tg];
        float2 b = *(const float2*)&g_P.M[fg][8 + 2 * tg];
        mz = make_float4(a.x, a.y, b.x, b.y);
        ezv = g_P.ez[fg];
    }

    const int totalWarps = gridDim.x * 4;
    for (int s0 = (blockIdx.x * 4 + wid) * 2; s0 < nB; s0 += totalWarps * 2) {
        // ---- coalesced load of BOTH samples, staged at stride 20 ----
        __syncwarp();                        // prior iteration's Vt reads done
        {
            const float4* gp = (const float4*)(x + (long long)s0 * 224);
            #pragma unroll
            for (int j = 0; j < 4; j++) {
                const int i = lane + 32 * j;          // 0..127, need 0..111
                if (i < 112) {
                    const int sm2 = (i >= 56);
                    const int ii  = i - 56 * sm2;     // float4 idx within sample
                    const float4 v = __ldg(gp + i);
                    float* dst = smT[wid][sm2];
                    *(float4*)&dst[(ii >> 2) * 20 + ((ii & 3) << 2)] = v;
                }
            }
        }
        __syncwarp();

        #pragma unroll
        for (int smp = 0; smp < 2; smp++) {
            const int samp = s0 + smp;
            float* Tile = smT[wid][smp];     // stage (stride 20), then Vt (24)

            // ---- gather x in fragment layout (bank-perfect LDS.32) ----
            float xlo[4], xhi[4];
            #pragma unroll
            for (int u = 0; u < 4; u++) {
                xlo[u] = Tile[fg * 20 + tg + 4 * u];
                xhi[u] = (fg < 6) ? Tile[(fg + 8) * 20 + tg + 4 * u] : 0.f;
            }
            // ---- LN via quad shuffles ----
            float s1l = ((xlo[0] + xlo[1]) + (xlo[2] + xlo[3]));
            float s2l = xlo[0] * xlo[0];
            s2l = fmaf(xlo[1], xlo[1], s2l); s2l = fmaf(xlo[2], xlo[2], s2l); s2l = fmaf(xlo[3], xlo[3], s2l);
            float s1h = ((xhi[0] + xhi[1]) + (xhi[2] + xhi[3]));
            float s2h = xhi[0] * xhi[0];
            s2h = fmaf(xhi[1], xhi[1], s2h); s2h = fmaf(xhi[2], xhi[2], s2h); s2h = fmaf(xhi[3], xhi[3], s2h);
            s1l += __shfl_xor_sync(FULLM, s1l, 1); s1l += __shfl_xor_sync(FULLM, s1l, 2);
            s2l += __shfl_xor_sync(FULLM, s2l, 1); s2l += __shfl_xor_sync(FULLM, s2l, 2);
            s1h += __shfl_xor_sync(FULLM, s1h, 1); s1h += __shfl_xor_sync(FULLM, s1h, 2);
            s2h += __shfl_xor_sync(FULLM, s2h, 1); s2h += __shfl_xor_sync(FULLM, s2h, 2);
            const float mL = s1l * 0.0625f;
            const float rL = rsqrtf(fmaf(-mL, mL, s2l * 0.0625f) + LN_EPS);
            const float mH = s1h * 0.0625f;
            const float rH = rsqrtf(fmaf(-mH, mH, s2h * 0.0625f) + LN_EPS);
            u32 a0 = f2t((xlo[0] - mL) * rL), a1 = f2t((xhi[0] - mH) * rH);
            u32 a2 = f2t((xlo[1] - mL) * rL), a3 = f2t((xhi[1] - mH) * rH);
            u32 a4 = f2t((xlo[2] - mL) * rL), a5 = f2t((xhi[2] - mH) * rH);
            u32 a6 = f2t((xlo[3] - mL) * rL), a7 = f2t((xhi[3] - mH) * rH);

            // ---- QKV (PI-permuted): C-frags land in true-d layout ----
            float Q[8], K[8], V[8];
            #pragma unroll
            for (int p = 0; p < 3; p++) {
                float* D = (p == 0) ? Q : ((p == 1) ? K : V);
                #pragma unroll
                for (int nt = 0; nt < 2; nt++) {
                    float d0, d1, d2, d3;
                    mma8(d0, d1, d2, d3, a0, a1, a2, a3,
                         bw[p][nt][0][0], bw[p][nt][0][1],
                         bs[p][nt][0], bs[p][nt][1], bs[p][nt][0], bs[p][nt][1]);
                    mma8(d0, d1, d2, d3, a4, a5, a6, a7,
                         bw[p][nt][1][0], bw[p][nt][1][1], d0, d1, d2, d3);
                    D[nt * 4 + 0] = d0; D[nt * 4 + 1] = d1;
                    D[nt * 4 + 2] = d2; D[nt * 4 + 3] = d3;
                }
            }

            // ---- stage V transposed: Vt[d][key], stride 24 (conflict-free) ----
            __syncwarp();                    // all lanes done reading staged x
            Tile[ tg       * 24 + fg    ] = V[0];
            Tile[(tg + 4)  * 24 + fg    ] = V[1];
            Tile[ tg       * 24 + fg + 8] = V[2];
            Tile[(tg + 4)  * 24 + fg + 8] = V[3];
            Tile[(tg + 8)  * 24 + fg    ] = V[4];
            Tile[(tg + 12) * 24 + fg    ] = V[5];
            Tile[(tg + 8)  * 24 + fg + 8] = V[6];
            Tile[(tg + 12) * 24 + fg + 8] = V[7];

            // ---- S = Q K^T : pure register MMA ----
            u32 qa0 = f2t(Q[0]), qa1 = f2t(Q[2]), qa2 = f2t(Q[1]), qa3 = f2t(Q[3]);
            u32 qa4 = f2t(Q[4]), qa5 = f2t(Q[6]), qa6 = f2t(Q[5]), qa7 = f2t(Q[7]);
            float t0, t1, t2, t3, u0, u1, u2, u3;
            mma8(t0, t1, t2, t3, qa0, qa1, qa2, qa3, f2t(K[0]), f2t(K[1]), 0.f, 0.f, 0.f, 0.f);
            mma8(t0, t1, t2, t3, qa4, qa5, qa6, qa7, f2t(K[4]), f2t(K[5]), t0, t1, t2, t3);
            mma8(u0, u1, u2, u3, qa0, qa1, qa2, qa3, f2t(K[2]), f2t(K[3]), 0.f, 0.f, 0.f, 0.f);
            mma8(u0, u1, u2, u3, qa4, qa5, qa6, qa7, f2t(K[6]), f2t(K[7]), u0, u1, u2, u3);
            if (tg == 3) { u0 = -1e30f; u1 = -1e30f; u2 = -1e30f; u3 = -1e30f; }  // keys 14,15

            // ---- softmax rows (quad shuffles), fold wm*inv into P ----
            float mLo = fmaxf(fmaxf(t0, t1), fmaxf(u0, u1));
            mLo = fmaxf(mLo, __shfl_xor_sync(FULLM, mLo, 1));
            mLo = fmaxf(mLo, __shfl_xor_sync(FULLM, mLo, 2));
            float mHi = fmaxf(fmaxf(t2, t3), fmaxf(u2, u3));
            mHi = fmaxf(mHi, __shfl_xor_sync(FULLM, mHi, 1));
            mHi = fmaxf(mHi, __shfl_xor_sync(FULLM, mHi, 2));
            float e0 = __expf(t0 - mLo), e1 = __expf(t1 - mLo), e4 = __expf(u0 - mLo), e5 = __expf(u1 - mLo);
            float e2 = __expf(t2 - mHi), e3 = __expf(t3 - mHi), e6 = __expf(u2 - mHi), e7 = __expf(u3 - mHi);
            float sl = (e0 + e1) + (e4 + e5);
            sl += __shfl_xor_sync(FULLM, sl, 1); sl += __shfl_xor_sync(FULLM, sl, 2);
            float sh = (e2 + e3) + (e6 + e7);
            sh += __shfl_xor_sync(FULLM, sh, 1); sh += __shfl_xor_sync(FULLM, sh, 2);
            const float wl = wmLo * __fdividef(1.f, sl);
            const float wh = wmHi * __fdividef(1.f, sh);
            u32 pa0 = f2t(e0 * wl), pa1 = f2t(e2 * wh), pa2 = f2t(e1 * wl), pa3 = f2t(e3 * wh);
            u32 pb0 = f2t(e4 * wl), pb1 = f2t(e6 * wh), pb2 = f2t(e5 * wl), pb3 = f2t(e7 * wh);

            __syncwarp();
            const float2 v00 = *(const float2*)&Tile[fg * 24 + 2 * tg];
            const float2 v01 = *(const float2*)&Tile[fg * 24 + 8 + 2 * tg];
            const float2 v10 = *(const float2*)&Tile[(fg + 8) * 24 + 2 * tg];
            const float2 v11 = *(const float2*)&Tile[(fg + 8) * 24 + 8 + 2 * tg];

            // ---- O = P' V (key dim permuted consistently on both sides) ----
            float o0, o1, o2, o3, p0, p1, p2, p3;
            mma8(o0, o1, o2, o3, pa0, pa1, pa2, pa3, f2t(v00.x), f2t(v00.y), 0.f, 0.f, 0.f, 0.f);
            mma8(o0, o1, o2, o3, pb0, pb1, pb2, pb3, f2t(v01.x), f2t(v01.y), o0, o1, o2, o3);
            mma8(p0, p1, p2, p3, pa0, pa1, pa2, pa3, f2t(v10.x), f2t(v10.y), 0.f, 0.f, 0.f, 0.f);
            mma8(p0, p1, p2, p3, pb0, pb1, pb2, pb3, f2t(v11.x), f2t(v11.y), p0, p1, p2, p3);

            // ---- t[d]: column sums over q (rows already weighted) ----
            float c0 = o0 + o2, c1 = o1 + o3, c2 = p0 + p2, c3 = p1 + p3;
            #pragma unroll
            for (int off = 4; off <= 16; off <<= 1) {
                c0 += __shfl_xor_sync(FULLM, c0, off);
                c1 += __shfl_xor_sync(FULLM, c1, off);
                c2 += __shfl_xor_sync(FULLM, c2, off);
                c3 += __shfl_xor_sync(FULLM, c3, off);
            }

            // ---- z[c] per fg-group (partial dot; ez added ONCE after quad sum) ----
            float z = (fg < 7)
                ? fmaf(mz.x, c0, fmaf(mz.y, c1, fmaf(mz.z, c2, mz.w * c3)))
                : 0.f;
            z += __shfl_xor_sync(FULLM, z, 1);
            z += __shfl_xor_sync(FULLM, z, 2);
            float zq = (fg < 7) ? (z + ezv) : -1e30f;
            float zm = zq;
            zm = fmaxf(zm, __shfl_xor_sync(FULLM, zm, 4));
            zm = fmaxf(zm, __shfl_xor_sync(FULLM, zm, 8));
            zm = fmaxf(zm, __shfl_xor_sync(FULLM, zm, 16));
            float ex = __expf(zq - zm);
            float se = ex;
            se += __shfl_xor_sync(FULLM, se, 4);
            se += __shfl_xor_sync(FULLM, se, 8);
            se += __shfl_xor_sync(FULLM, se, 16);
            if (tg == 0 && fg < 7)
                out[samp * 7 + fg] = __fdividef(ex, se);
        }
    }
}

extern "C" void kernel_launch(void* const* d_in, const int* in_sizes, int n_in,
                              void* d_out, int out_size)
{
    const float* sample = (const float*)d_in[0];
    setup_kernel<<<1, 256>>>(
        (const float*)d_in[1],  (const float*)d_in[2],
        (const float*)d_in[3],  (const float*)d_in[4],
        (const float*)d_in[5],  (const float*)d_in[6],
        (const float*)d_in[7],  (const float*)d_in[8],
        (const float*)d_in[9],  (const float*)d_in[10],
        (const float*)d_in[11], (const float*)d_in[12],
        (const float*)d_in[13], (const float*)d_in[14],
        (const float*)d_in[15], (const float*)d_in[16],
        (const float*)d_in[17], (const float*)d_in[18]);

    const int nB = in_sizes[0] / 224;   // B = 131072
    hopfield_kernel<<<2048, 128>>>(sample, (float*)d_out, nB);
}

// round 9
// speedup vs baseline: 1.1319x; 1.0295x over previous
#include <cuda_runtime.h>

// ---------------------------------------------------------------------------
// M1_17008070492428: batched tiny Hopfield attention + classifier head.
//   B=131072 samples, each (S=14, D=16) -> (7,) softmax probs.
// R8 = R7 minus the O = P@V MMA and the V smem transpose:
//   t[d] = sum_k r[k] V[k][d],  r[k] = sum_q wm[q]/Z_q * P[q][k],
//   computed by shuffle reductions directly on the P and V fragments.
//   Removes 4 MMAs, 8 STS, 4 LDS.64 and 2 in-pipeline __syncwarp()s per
//   sample; the two unrolled samples' chains can now interleave.
// Pipeline: PI-permuted QKV weights make each MMA C-fragment coincide with
// the next MMA's A/B fragment layout; x staged via smem (stride 20) for a
// coalesced LDG.128 + conflict-free LDS.32 gather; raw f32 bits as tf32.
// ---------------------------------------------------------------------------

typedef unsigned int u32;
#define LN_EPS 1e-5f
#define FULLM 0xffffffffu

__device__ __forceinline__ u32 f2t(float x) {          // f32 bits as tf32
    return __float_as_uint(x);
}
__device__ __forceinline__ void mma8(float& d0, float& d1, float& d2, float& d3,
                                     u32 a0, u32 a1, u32 a2, u32 a3,
                                     u32 b0, u32 b1,
                                     float c0, float c1, float c2, float c3) {
    asm("mma.sync.aligned.m16n8k8.row.col.f32.tf32.tf32.f32 "
        "{%0,%1,%2,%3},{%4,%5,%6,%7},{%8,%9},{%10,%11,%12,%13};"
        : "=f"(d0), "=f"(d1), "=f"(d2), "=f"(d3)
        : "r"(a0), "r"(a1), "r"(a2), "r"(a3), "r"(b0), "r"(b1),
          "f"(c0), "f"(c1), "f"(c2), "f"(c3));
}

struct __align__(16) Params {
    float wq[16][16], wk[16][16], wv[16][16];  // PI-permuted rows, LN-gamma folded
    float bq[16], bk[16], bv[16];              // PI-permuted, LN-beta folded
    float M[7][16];                            // Wb @ Wo (true-d columns)
    float ez[8];
    float wm[16];                              // Wm padded with zeros
};
__device__ Params g_P;

__global__ void setup_kernel(
    const float* __restrict__ lnqg, const float* __restrict__ lnqb,
    const float* __restrict__ lnkg, const float* __restrict__ lnkb,
    const float* __restrict__ lnvg, const float* __restrict__ lnvb,
    const float* __restrict__ Wq,  const float* __restrict__ bq,
    const float* __restrict__ Wk,  const float* __restrict__ bk,
    const float* __restrict__ Wv,  const float* __restrict__ bv,
    const float* __restrict__ Wo,  const float* __restrict__ bo,
    const float* __restrict__ Wm,  const float* __restrict__ bm,
    const float* __restrict__ Wb,  const float* __restrict__ bb)
{
    const int PI[16] = {0,4,1,5,2,6,3,7, 8,12,9,13,10,14,11,15};
    const int t = threadIdx.x;           // 256 threads, 1 block
    const int e = t >> 4, d = t & 15;
    const int pe = PI[e];
    g_P.wq[e][d] = Wq[pe * 16 + d] * lnqg[d];
    g_P.wk[e][d] = Wk[pe * 16 + d] * lnkg[d];
    g_P.wv[e][d] = Wv[pe * 16 + d] * lnvg[d];
    if (t < 16) {
        const int p = PI[t];
        float aq = bq[p], ak = bk[p], av = bv[p];
        #pragma unroll
        for (int i = 0; i < 16; i++) {
            aq = fmaf(lnqb[i], Wq[p * 16 + i], aq);
            ak = fmaf(lnkb[i], Wk[p * 16 + i], ak);
            av = fmaf(lnvb[i], Wv[p * 16 + i], av);
        }
        g_P.bq[t] = aq; g_P.bk[t] = ak; g_P.bv[t] = av;
        g_P.wm[t] = (t < 14) ? Wm[t] : 0.f;
    }
    if (t < 112) {
        const int c = t >> 4, dd = t & 15;
        float s = 0.f;
        for (int o = 0; o < 128; o++)
            s = fmaf(Wb[c * 128 + o], Wo[o * 16 + dd], s);
        g_P.M[c][dd] = s;
    }
    if (t >= 112 && t < 119) {
        const int c = t - 112;
        float c0 = 0.f;
        for (int s = 0; s < 14; s++) c0 += Wm[s];
        float z = bb[c];
        const float bmv = bm[0];
        for (int o = 0; o < 128; o++)
            z = fmaf(Wb[c * 128 + o], fmaf(c0, bo[o], bmv), z);
        g_P.ez[c] = z;
    }
    if (t == 119) g_P.ez[7] = 0.f;
}

__global__ __launch_bounds__(128, 4) void hopfield_kernel(
    const float* __restrict__ x, float* __restrict__ out, int nB)
{
    __shared__ __align__(16) float smT[4][2][16 * 20];   // input staging only
    const int tid  = threadIdx.x;
    const int lane = tid & 31;
    const int wid  = tid >> 5;
    const int fg   = lane >> 2;     // 0..7  (row group / B n-col)
    const int tg   = lane & 3;      // 0..3  (thread-in-quad)

    // ---- persistent weight B-fragments (raw f32 = truncated tf32) ----
    u32   bw[3][2][2][2];           // [proj][ntile][kstep][reg]
    float bs[3][2][2];
    {
        const float* Wp[3] = { &g_P.wq[0][0], &g_P.wk[0][0], &g_P.wv[0][0] };
        const float* Bp[3] = { g_P.bq, g_P.bk, g_P.bv };
        #pragma unroll
        for (int p = 0; p < 3; p++) {
            #pragma unroll
            for (int nt = 0; nt < 2; nt++) {
                #pragma unroll
                for (int ks = 0; ks < 2; ks++) {
                    const float* base = Wp[p] + (fg + 8 * nt) * 16 + 8 * ks;
                    bw[p][nt][ks][0] = f2t(__ldg(base + tg));
                    bw[p][nt][ks][1] = f2t(__ldg(base + tg + 4));
                }
                bs[p][nt][0] = __ldg(Bp[p] + 2 * tg + 8 * nt);
                bs[p][nt][1] = __ldg(Bp[p] + 2 * tg + 8 * nt + 1);
            }
        }
    }
    const float wmLo = g_P.wm[fg];
    const float wmHi = g_P.wm[fg + 8];      // 0 for rows 14,15
    float4 mz = make_float4(0.f, 0.f, 0.f, 0.f);
    float ezv = 0.f;
    if (fg < 7) {
        float2 a = *(const float2*)&g_P.M[fg][2 * tg];
        float2 b = *(const float2*)&g_P.M[fg][8 + 2 * tg];
        mz = make_float4(a.x, a.y, b.x, b.y);
        ezv = g_P.ez[fg];
    }
    const int rsel = fg >> 1;        // realign shuffle source lane
    const bool rodd = (fg & 1);

    const int totalWarps = gridDim.x * 4;
    for (int s0 = (blockIdx.x * 4 + wid) * 2; s0 < nB; s0 += totalWarps * 2) {
        // ---- coalesced load of BOTH samples, staged at stride 20 ----
        __syncwarp();                        // prior iteration's gathers done
        {
            const float4* gp = (const float4*)(x + (long long)s0 * 224);
            #pragma unroll
            for (int j = 0; j < 4; j++) {
                const int i = lane + 32 * j;          // 0..127, need 0..111
                if (i < 112) {
                    const int sm2 = (i >= 56);
                    const int ii  = i - 56 * sm2;     // float4 idx within sample
                    const float4 v = __ldg(gp + i);
                    float* dst = smT[wid][sm2];
                    *(float4*)&dst[(ii >> 2) * 20 + ((ii & 3) << 2)] = v;
                }
            }
        }
        __syncwarp();

        #pragma unroll
        for (int smp = 0; smp < 2; smp++) {
            const int samp = s0 + smp;
            const float* Tile = smT[wid][smp];

            // ---- gather x in fragment layout (bank-perfect LDS.32) ----
            float xlo[4], xhi[4];
            #pragma unroll
            for (int u = 0; u < 4; u++) {
                xlo[u] = Tile[fg * 20 + tg + 4 * u];
                xhi[u] = (fg < 6) ? Tile[(fg + 8) * 20 + tg + 4 * u] : 0.f;
            }
            // ---- LN via quad shuffles ----
            float s1l = ((xlo[0] + xlo[1]) + (xlo[2] + xlo[3]));
            float s2l = xlo[0] * xlo[0];
            s2l = fmaf(xlo[1], xlo[1], s2l); s2l = fmaf(xlo[2], xlo[2], s2l); s2l = fmaf(xlo[3], xlo[3], s2l);
            float s1h = ((xhi[0] + xhi[1]) + (xhi[2] + xhi[3]));
            float s2h = xhi[0] * xhi[0];
            s2h = fmaf(xhi[1], xhi[1], s2h); s2h = fmaf(xhi[2], xhi[2], s2h); s2h = fmaf(xhi[3], xhi[3], s2h);
            s1l += __shfl_xor_sync(FULLM, s1l, 1); s1l += __shfl_xor_sync(FULLM, s1l, 2);
            s2l += __shfl_xor_sync(FULLM, s2l, 1); s2l += __shfl_xor_sync(FULLM, s2l, 2);
            s1h += __shfl_xor_sync(FULLM, s1h, 1); s1h += __shfl_xor_sync(FULLM, s1h, 2);
            s2h += __shfl_xor_sync(FULLM, s2h, 1); s2h += __shfl_xor_sync(FULLM, s2h, 2);
            const float mL = s1l * 0.0625f;
            const float rL = rsqrtf(fmaf(-mL, mL, s2l * 0.0625f) + LN_EPS);
            const float mH = s1h * 0.0625f;
            const float rH = rsqrtf(fmaf(-mH, mH, s2h * 0.0625f) + LN_EPS);
            u32 a0 = f2t((xlo[0] - mL) * rL), a1 = f2t((xhi[0] - mH) * rH);
            u32 a2 = f2t((xlo[1] - mL) * rL), a3 = f2t((xhi[1] - mH) * rH);
            u32 a4 = f2t((xlo[2] - mL) * rL), a5 = f2t((xhi[2] - mH) * rH);
            u32 a6 = f2t((xlo[3] - mL) * rL), a7 = f2t((xhi[3] - mH) * rH);

            // ---- QKV (PI-permuted): C-frags land in true-d layout ----
            float Q[8], K[8], V[8];
            #pragma unroll
            for (int p = 0; p < 3; p++) {
                float* D = (p == 0) ? Q : ((p == 1) ? K : V);
                #pragma unroll
                for (int nt = 0; nt < 2; nt++) {
                    float d0, d1, d2, d3;
                    mma8(d0, d1, d2, d3, a0, a1, a2, a3,
                         bw[p][nt][0][0], bw[p][nt][0][1],
                         bs[p][nt][0], bs[p][nt][1], bs[p][nt][0], bs[p][nt][1]);
                    mma8(d0, d1, d2, d3, a4, a5, a6, a7,
                         bw[p][nt][1][0], bw[p][nt][1][1], d0, d1, d2, d3);
                    D[nt * 4 + 0] = d0; D[nt * 4 + 1] = d1;
                    D[nt * 4 + 2] = d2; D[nt * 4 + 3] = d3;
                }
            }

            // ---- S = Q K^T : pure register MMA (cols = true keys) ----
            u32 qa0 = f2t(Q[0]), qa1 = f2t(Q[2]), qa2 = f2t(Q[1]), qa3 = f2t(Q[3]);
            u32 qa4 = f2t(Q[4]), qa5 = f2t(Q[6]), qa6 = f2t(Q[5]), qa7 = f2t(Q[7]);
            float t0, t1, t2, t3, u0, u1, u2, u3;
            mma8(t0, t1, t2, t3, qa0, qa1, qa2, qa3, f2t(K[0]), f2t(K[1]), 0.f, 0.f, 0.f, 0.f);
            mma8(t0, t1, t2, t3, qa4, qa5, qa6, qa7, f2t(K[4]), f2t(K[5]), t0, t1, t2, t3);
            mma8(u0, u1, u2, u3, qa0, qa1, qa2, qa3, f2t(K[2]), f2t(K[3]), 0.f, 0.f, 0.f, 0.f);
            mma8(u0, u1, u2, u3, qa4, qa5, qa6, qa7, f2t(K[6]), f2t(K[7]), u0, u1, u2, u3);
            if (tg == 3) { u0 = -1e30f; u1 = -1e30f; u2 = -1e30f; u3 = -1e30f; }  // keys 14,15

            // ---- softmax rows (quad shuffles), weights wm/Z folded in ----
            float mLo = fmaxf(fmaxf(t0, t1), fmaxf(u0, u1));
            mLo = fmaxf(mLo, __shfl_xor_sync(FULLM, mLo, 1));
            mLo = fmaxf(mLo, __shfl_xor_sync(FULLM, mLo, 2));
            float mHi = fmaxf(fmaxf(t2, t3), fmaxf(u2, u3));
            mHi = fmaxf(mHi, __shfl_xor_sync(FULLM, mHi, 1));
            mHi = fmaxf(mHi, __shfl_xor_sync(FULLM, mHi, 2));
            float e0 = __expf(t0 - mLo), e1 = __expf(t1 - mLo), e4 = __expf(u0 - mLo), e5 = __expf(u1 - mLo);
            float e2 = __expf(t2 - mHi), e3 = __expf(t3 - mHi), e6 = __expf(u2 - mHi), e7 = __expf(u3 - mHi);
            float sl = (e0 + e1) + (e4 + e5);
            sl += __shfl_xor_sync(FULLM, sl, 1); sl += __shfl_xor_sync(FULLM, sl, 2);
            float sh = (e2 + e3) + (e6 + e7);
            sh += __shfl_xor_sync(FULLM, sh, 1); sh += __shfl_xor_sync(FULLM, sh, 2);
            const float wl = wmLo * __fdividef(1.f, sl);
            const float wh = wmHi * __fdividef(1.f, sh);

            // ---- r[key] = sum_q wP[q][key]  (reduce over fg) ----
            float rA = fmaf(e0, wl, e2 * wh);        // key = 2tg
            float rB = fmaf(e1, wl, e3 * wh);        // key = 2tg+1
            float rC = fmaf(e4, wl, e6 * wh);        // key = 8+2tg
            float rD = fmaf(e5, wl, e7 * wh);        // key = 8+2tg+1
            #pragma unroll
            for (int off = 4; off <= 16; off <<= 1) {
                rA += __shfl_xor_sync(FULLM, rA, off);
                rB += __shfl_xor_sync(FULLM, rB, off);
                rC += __shfl_xor_sync(FULLM, rC, off);
                rD += __shfl_xor_sync(FULLM, rD, off);
            }
            // realign: r_lo = r[fg], r_hi = r[fg+8]
            const float rAs = __shfl_sync(FULLM, rA, rsel);
            const float rBs = __shfl_sync(FULLM, rB, rsel);
            const float rCs = __shfl_sync(FULLM, rC, rsel);
            const float rDs = __shfl_sync(FULLM, rD, rsel);
            const float r_lo = rodd ? rBs : rAs;
            const float r_hi = rodd ? rDs : rCs;

            // ---- t[d] = sum_k r[k] V[k][d]  (V frags already in registers) ----
            float td0 = fmaf(r_lo, V[0], r_hi * V[2]);   // d = 2tg
            float td1 = fmaf(r_lo, V[1], r_hi * V[3]);   // d = 2tg+1
            float td2 = fmaf(r_lo, V[4], r_hi * V[6]);   // d = 8+2tg
            float td3 = fmaf(r_lo, V[5], r_hi * V[7]);   // d = 8+2tg+1
            #pragma unroll
            for (int off = 4; off <= 16; off <<= 1) {
                td0 += __shfl_xor_sync(FULLM, td0, off);
                td1 += __shfl_xor_sync(FULLM, td1, off);
                td2 += __shfl_xor_sync(FULLM, td2, off);
                td3 += __shfl_xor_sync(FULLM, td3, off);
            }

            // ---- z[c] per fg-group (partial dot; ez added ONCE after quad sum) ----
            float z = (fg < 7)
                ? fmaf(mz.x, td0, fmaf(mz.y, td1, fmaf(mz.z, td2, mz.w * td3)))
                : 0.f;
            z += __shfl_xor_sync(FULLM, z, 1);
            z += __shfl_xor_sync(FULLM, z, 2);
            float zq = (fg < 7) ? (z + ezv) : -1e30f;
            float zm = zq;
            zm = fmaxf(zm, __shfl_xor_sync(FULLM, zm, 4));
            zm = fmaxf(zm, __shfl_xor_sync(FULLM, zm, 8));
            zm = fmaxf(zm, __shfl_xor_sync(FULLM, zm, 16));
            float ex = __expf(zq - zm);
            float se = ex;
            se += __shfl_xor_sync(FULLM, se, 4);
            se += __shfl_xor_sync(FULLM, se, 8);
            se += __shfl_xor_sync(FULLM, se, 16);
            if (tg == 0 && fg < 7)
                out[samp * 7 + fg] = __fdividef(ex, se);
        }
    }
}

extern "C" void kernel_launch(void* const* d_in, const int* in_sizes, int n_in,
                              void* d_out, int out_size)
{
    const float* sample = (const float*)d_in[0];
    setup_kernel<<<1, 256>>>(
        (const float*)d_in[1],  (const float*)d_in[2],
        (const float*)d_in[3],  (const float*)d_in[4],
        (const float*)d_in[5],  (const float*)d_in[6],
        (const float*)d_in[7],  (const float*)d_in[8],
        (const float*)d_in[9],  (const float*)d_in[10],
        (const float*)d_in[11], (const float*)d_in[12],
        (const float*)d_in[13], (const float*)d_in[14],
        (const float*)d_in[15], (const float*)d_in[16],
        (const float*)d_in[17], (const float*)d_in[18]);

    const int nB = in_sizes[0] / 224;   // B = 131072
    hopfield_kernel<<<2048, 128>>>(sample, (float*)d_out, nB);
}

// round 10
// speedup vs baseline: 1.1577x; 1.0227x over previous
#include <cuda_runtime.h>

// ---------------------------------------------------------------------------
// M1_17008070492428: batched tiny Hopfield attention + classifier head.
//   B=131072 samples, each (S=14, D=16) -> (7,) softmax probs.
// R9 = R8 + CORRECTNESS FIX: the QKV C-fragment columns are PI-permuted
//   (col e = true d PI[e]), so the fragment-resident t vector is
//   {t[tg], t[tg+4], t[8+tg], t[12+tg]}. R8 paired it with M at true-d
//   columns -> permuted dot product (silent ~6e-4 error). Fix: store M
//   PI-permuted in setup so mz pairs with td correctly.
//   Also removed the max-subtraction in the 7-class softmax (z is O(1),
//   exp cannot overflow) to shorten the tail dependency chain.
// Pipeline: register-resident MMA QKV + S=QK^T; r[k]=sum_q wm_q/Z_q P[q,k]
// and t=r@V via shuffle reductions on fragments; x staged through smem
// (stride 20) for coalesced LDG.128 + conflict-free LDS.32.
// ---------------------------------------------------------------------------

typedef unsigned int u32;
#define LN_EPS 1e-5f
#define FULLM 0xffffffffu

__device__ __forceinline__ u32 f2t(float x) {          // f32 bits as tf32
    return __float_as_uint(x);
}
__device__ __forceinline__ void mma8(float& d0, float& d1, float& d2, float& d3,
                                     u32 a0, u32 a1, u32 a2, u32 a3,
                                     u32 b0, u32 b1,
                                     float c0, float c1, float c2, float c3) {
    asm("mma.sync.aligned.m16n8k8.row.col.f32.tf32.tf32.f32 "
        "{%0,%1,%2,%3},{%4,%5,%6,%7},{%8,%9},{%10,%11,%12,%13};"
        : "=f"(d0), "=f"(d1), "=f"(d2), "=f"(d3)
        : "r"(a0), "r"(a1), "r"(a2), "r"(a3), "r"(b0), "r"(b1),
          "f"(c0), "f"(c1), "f"(c2), "f"(c3));
}

struct __align__(16) Params {
    float wq[16][16], wk[16][16], wv[16][16];  // PI-permuted rows, LN-gamma folded
    float bq[16], bk[16], bv[16];              // PI-permuted, LN-beta folded
    float M[7][16];                            // (Wb@Wo) with PI-permuted columns
    float ez[8];
    float wm[16];                              // Wm padded with zeros
};
__device__ Params g_P;

__global__ void setup_kernel(
    const float* __restrict__ lnqg, const float* __restrict__ lnqb,
    const float* __restrict__ lnkg, const float* __restrict__ lnkb,
    const float* __restrict__ lnvg, const float* __restrict__ lnvb,
    const float* __restrict__ Wq,  const float* __restrict__ bq,
    const float* __restrict__ Wk,  const float* __restrict__ bk,
    const float* __restrict__ Wv,  const float* __restrict__ bv,
    const float* __restrict__ Wo,  const float* __restrict__ bo,
    const float* __restrict__ Wm,  const float* __restrict__ bm,
    const float* __restrict__ Wb,  const float* __restrict__ bb)
{
    const int PI[16] = {0,4,1,5,2,6,3,7, 8,12,9,13,10,14,11,15};
    const int t = threadIdx.x;           // 256 threads, 1 block
    const int e = t >> 4, d = t & 15;
    const int pe = PI[e];
    g_P.wq[e][d] = Wq[pe * 16 + d] * lnqg[d];
    g_P.wk[e][d] = Wk[pe * 16 + d] * lnkg[d];
    g_P.wv[e][d] = Wv[pe * 16 + d] * lnvg[d];
    if (t < 16) {
        const int p = PI[t];
        float aq = bq[p], ak = bk[p], av = bv[p];
        #pragma unroll
        for (int i = 0; i < 16; i++) {
            aq = fmaf(lnqb[i], Wq[p * 16 + i], aq);
            ak = fmaf(lnkb[i], Wk[p * 16 + i], ak);
            av = fmaf(lnvb[i], Wv[p * 16 + i], av);
        }
        g_P.bq[t] = aq; g_P.bk[t] = ak; g_P.bv[t] = av;
        g_P.wm[t] = (t < 14) ? Wm[t] : 0.f;
    }
    if (t < 112) {
        const int c = t >> 4, dd = t & 15;
        const int pd = PI[dd];               // FIX: PI-permuted M columns
        float s = 0.f;
        for (int o = 0; o < 128; o++)
            s = fmaf(Wb[c * 128 + o], Wo[o * 16 + pd], s);
        g_P.M[c][dd] = s;
    }
    if (t >= 112 && t < 119) {
        const int c = t - 112;
        float c0 = 0.f;
        for (int s = 0; s < 14; s++) c0 += Wm[s];
        float z = bb[c];
        const float bmv = bm[0];
        for (int o = 0; o < 128; o++)
            z = fmaf(Wb[c * 128 + o], fmaf(c0, bo[o], bmv), z);
        g_P.ez[c] = z;
    }
    if (t == 119) g_P.ez[7] = 0.f;
}

__global__ __launch_bounds__(128, 4) void hopfield_kernel(
    const float* __restrict__ x, float* __restrict__ out, int nB)
{
    __shared__ __align__(16) float smT[4][2][16 * 20];   // input staging only
    const int tid  = threadIdx.x;
    const int lane = tid & 31;
    const int wid  = tid >> 5;
    const int fg   = lane >> 2;     // 0..7  (row group / B n-col)
    const int tg   = lane & 3;      // 0..3  (thread-in-quad)

    // ---- persistent weight B-fragments (raw f32 = truncated tf32) ----
    u32   bw[3][2][2][2];           // [proj][ntile][kstep][reg]
    float bs[3][2][2];
    {
        const float* Wp[3] = { &g_P.wq[0][0], &g_P.wk[0][0], &g_P.wv[0][0] };
        const float* Bp[3] = { g_P.bq, g_P.bk, g_P.bv };
        #pragma unroll
        for (int p = 0; p < 3; p++) {
            #pragma unroll
            for (int nt = 0; nt < 2; nt++) {
                #pragma unroll
                for (int ks = 0; ks < 2; ks++) {
                    const float* base = Wp[p] + (fg + 8 * nt) * 16 + 8 * ks;
                    bw[p][nt][ks][0] = f2t(__ldg(base + tg));
                    bw[p][nt][ks][1] = f2t(__ldg(base + tg + 4));
                }
                bs[p][nt][0] = __ldg(Bp[p] + 2 * tg + 8 * nt);
                bs[p][nt][1] = __ldg(Bp[p] + 2 * tg + 8 * nt + 1);
            }
        }
    }
    const float wmLo = g_P.wm[fg];
    const float wmHi = g_P.wm[fg + 8];      // 0 for rows 14,15
    float4 mz = make_float4(0.f, 0.f, 0.f, 0.f);
    float ezv = 0.f;
    if (fg < 7) {
        float2 a = *(const float2*)&g_P.M[fg][2 * tg];      // PI cols: pair with td
        float2 b = *(const float2*)&g_P.M[fg][8 + 2 * tg];
        mz = make_float4(a.x, a.y, b.x, b.y);
        ezv = g_P.ez[fg];
    }
    const int rsel = fg >> 1;        // realign shuffle source lane
    const bool rodd = (fg & 1);

    const int totalWarps = gridDim.x * 4;
    for (int s0 = (blockIdx.x * 4 + wid) * 2; s0 < nB; s0 += totalWarps * 2) {
        // ---- coalesced load of BOTH samples, staged at stride 20 ----
        __syncwarp();                        // prior iteration's gathers done
        {
            const float4* gp = (const float4*)(x + (long long)s0 * 224);
            #pragma unroll
            for (int j = 0; j < 4; j++) {
                const int i = lane + 32 * j;          // 0..127, need 0..111
                if (i < 112) {
                    const int sm2 = (i >= 56);
                    const int ii  = i - 56 * sm2;     // float4 idx within sample
                    const float4 v = __ldg(gp + i);
                    float* dst = smT[wid][sm2];
                    *(float4*)&dst[(ii >> 2) * 20 + ((ii & 3) << 2)] = v;
                }
            }
        }
        __syncwarp();

        #pragma unroll
        for (int smp = 0; smp < 2; smp++) {
            const int samp = s0 + smp;
            const float* Tile = smT[wid][smp];

            // ---- gather x in fragment layout (bank-perfect LDS.32) ----
            float xlo[4], xhi[4];
            #pragma unroll
            for (int u = 0; u < 4; u++) {
                xlo[u] = Tile[fg * 20 + tg + 4 * u];
                xhi[u] = (fg < 6) ? Tile[(fg + 8) * 20 + tg + 4 * u] : 0.f;
            }
            // ---- LN via quad shuffles ----
            float s1l = ((xlo[0] + xlo[1]) + (xlo[2] + xlo[3]));
            float s2l = xlo[0] * xlo[0];
            s2l = fmaf(xlo[1], xlo[1], s2l); s2l = fmaf(xlo[2], xlo[2], s2l); s2l = fmaf(xlo[3], xlo[3], s2l);
            float s1h = ((xhi[0] + xhi[1]) + (xhi[2] + xhi[3]));
            float s2h = xhi[0] * xhi[0];
            s2h = fmaf(xhi[1], xhi[1], s2h); s2h = fmaf(xhi[2], xhi[2], s2h); s2h = fmaf(xhi[3], xhi[3], s2h);
            s1l += __shfl_xor_sync(FULLM, s1l, 1); s1l += __shfl_xor_sync(FULLM, s1l, 2);
            s2l += __shfl_xor_sync(FULLM, s2l, 1); s2l += __shfl_xor_sync(FULLM, s2l, 2);
            s1h += __shfl_xor_sync(FULLM, s1h, 1); s1h += __shfl_xor_sync(FULLM, s1h, 2);
            s2h += __shfl_xor_sync(FULLM, s2h, 1); s2h += __shfl_xor_sync(FULLM, s2h, 2);
            const float mL = s1l * 0.0625f;
            const float rL = rsqrtf(fmaf(-mL, mL, s2l * 0.0625f) + LN_EPS);
            const float mH = s1h * 0.0625f;
            const float rH = rsqrtf(fmaf(-mH, mH, s2h * 0.0625f) + LN_EPS);
            u32 a0 = f2t((xlo[0] - mL) * rL), a1 = f2t((xhi[0] - mH) * rH);
            u32 a2 = f2t((xlo[1] - mL) * rL), a3 = f2t((xhi[1] - mH) * rH);
            u32 a4 = f2t((xlo[2] - mL) * rL), a5 = f2t((xhi[2] - mH) * rH);
            u32 a6 = f2t((xlo[3] - mL) * rL), a7 = f2t((xhi[3] - mH) * rH);

            // ---- QKV (PI-permuted cols): D[:,e] = proj_true[:, PI[e]] ----
            float Q[8], K[8], V[8];
            #pragma unroll
            for (int p = 0; p < 3; p++) {
                float* D = (p == 0) ? Q : ((p == 1) ? K : V);
                #pragma unroll
                for (int nt = 0; nt < 2; nt++) {
                    float d0, d1, d2, d3;
                    mma8(d0, d1, d2, d3, a0, a1, a2, a3,
                         bw[p][nt][0][0], bw[p][nt][0][1],
                         bs[p][nt][0], bs[p][nt][1], bs[p][nt][0], bs[p][nt][1]);
                    mma8(d0, d1, d2, d3, a4, a5, a6, a7,
                         bw[p][nt][1][0], bw[p][nt][1][1], d0, d1, d2, d3);
                    D[nt * 4 + 0] = d0; D[nt * 4 + 1] = d1;
                    D[nt * 4 + 2] = d2; D[nt * 4 + 3] = d3;
                }
            }

            // ---- S = Q K^T : pure register MMA (cols = true keys) ----
            u32 qa0 = f2t(Q[0]), qa1 = f2t(Q[2]), qa2 = f2t(Q[1]), qa3 = f2t(Q[3]);
            u32 qa4 = f2t(Q[4]), qa5 = f2t(Q[6]), qa6 = f2t(Q[5]), qa7 = f2t(Q[7]);
            float t0, t1, t2, t3, u0, u1, u2, u3;
            mma8(t0, t1, t2, t3, qa0, qa1, qa2, qa3, f2t(K[0]), f2t(K[1]), 0.f, 0.f, 0.f, 0.f);
            mma8(t0, t1, t2, t3, qa4, qa5, qa6, qa7, f2t(K[4]), f2t(K[5]), t0, t1, t2, t3);
            mma8(u0, u1, u2, u3, qa0, qa1, qa2, qa3, f2t(K[2]), f2t(K[3]), 0.f, 0.f, 0.f, 0.f);
            mma8(u0, u1, u2, u3, qa4, qa5, qa6, qa7, f2t(K[6]), f2t(K[7]), u0, u1, u2, u3);
            if (tg == 3) { u0 = -1e30f; u1 = -1e30f; u2 = -1e30f; u3 = -1e30f; }  // keys 14,15

            // ---- softmax rows (quad shuffles), weights wm/Z folded in ----
            float mLo = fmaxf(fmaxf(t0, t1), fmaxf(u0, u1));
            mLo = fmaxf(mLo, __shfl_xor_sync(FULLM, mLo, 1));
            mLo = fmaxf(mLo, __shfl_xor_sync(FULLM, mLo, 2));
            float mHi = fmaxf(fmaxf(t2, t3), fmaxf(u2, u3));
            mHi = fmaxf(mHi, __shfl_xor_sync(FULLM, mHi, 1));
            mHi = fmaxf(mHi, __shfl_xor_sync(FULLM, mHi, 2));
            float e0 = __expf(t0 - mLo), e1 = __expf(t1 - mLo), e4 = __expf(u0 - mLo), e5 = __expf(u1 - mLo);
            float e2 = __expf(t2 - mHi), e3 = __expf(t3 - mHi), e6 = __expf(u2 - mHi), e7 = __expf(u3 - mHi);
            float sl = (e0 + e1) + (e4 + e5);
            sl += __shfl_xor_sync(FULLM, sl, 1); sl += __shfl_xor_sync(FULLM, sl, 2);
            float sh = (e2 + e3) + (e6 + e7);
            sh += __shfl_xor_sync(FULLM, sh, 1); sh += __shfl_xor_sync(FULLM, sh, 2);
            const float wl = wmLo * __fdividef(1.f, sl);
            const float wh = wmHi * __fdividef(1.f, sh);

            // ---- r[key] = sum_q wP[q][key]  (reduce over fg) ----
            float rA = fmaf(e0, wl, e2 * wh);        // key = 2tg
            float rB = fmaf(e1, wl, e3 * wh);        // key = 2tg+1
            float rC = fmaf(e4, wl, e6 * wh);        // key = 8+2tg
            float rD = fmaf(e5, wl, e7 * wh);        // key = 8+2tg+1
            #pragma unroll
            for (int off = 4; off <= 16; off <<= 1) {
                rA += __shfl_xor_sync(FULLM, rA, off);
                rB += __shfl_xor_sync(FULLM, rB, off);
                rC += __shfl_xor_sync(FULLM, rC, off);
                rD += __shfl_xor_sync(FULLM, rD, off);
            }
            // realign: r_lo = r[fg], r_hi = r[fg+8]
            const float rAs = __shfl_sync(FULLM, rA, rsel);
            const float rBs = __shfl_sync(FULLM, rB, rsel);
            const float rCs = __shfl_sync(FULLM, rC, rsel);
            const float rDs = __shfl_sync(FULLM, rD, rsel);
            const float r_lo = rodd ? rBs : rAs;
            const float r_hi = rodd ? rDs : rCs;

            // ---- t over PI-cols: td0..td3 = t[PI[2tg]], t[PI[2tg+1]], ... ----
            float td0 = fmaf(r_lo, V[0], r_hi * V[2]);
            float td1 = fmaf(r_lo, V[1], r_hi * V[3]);
            float td2 = fmaf(r_lo, V[4], r_hi * V[6]);
            float td3 = fmaf(r_lo, V[5], r_hi * V[7]);
            #pragma unroll
            for (int off = 4; off <= 16; off <<= 1) {
                td0 += __shfl_xor_sync(FULLM, td0, off);
                td1 += __shfl_xor_sync(FULLM, td1, off);
                td2 += __shfl_xor_sync(FULLM, td2, off);
                td3 += __shfl_xor_sync(FULLM, td3, off);
            }

            // ---- z[c]: M stored PI-permuted, so mz pairs with td exactly ----
            float z = (fg < 7)
                ? fmaf(mz.x, td0, fmaf(mz.y, td1, fmaf(mz.z, td2, mz.w * td3)))
                : 0.f;
            z += __shfl_xor_sync(FULLM, z, 1);
            z += __shfl_xor_sync(FULLM, z, 2);
            // 7-class softmax without max-shift: |z| is O(1), no overflow risk
            float ex = (fg < 7) ? __expf(z + ezv) : 0.f;
            float se = ex;
            se += __shfl_xor_sync(FULLM, se, 4);
            se += __shfl_xor_sync(FULLM, se, 8);
            se += __shfl_xor_sync(FULLM, se, 16);
            if (tg == 0 && fg < 7)
                out[samp * 7 + fg] = __fdividef(ex, se);
        }
    }
}

extern "C" void kernel_launch(void* const* d_in, const int* in_sizes, int n_in,
                              void* d_out, int out_size)
{
    const float* sample = (const float*)d_in[0];
    setup_kernel<<<1, 256>>>(
        (const float*)d_in[1],  (const float*)d_in[2],
        (const float*)d_in[3],  (const float*)d_in[4],
        (const float*)d_in[5],  (const float*)d_in[6],
        (const float*)d_in[7],  (const float*)d_in[8],
        (const float*)d_in[9],  (const float*)d_in[10],
        (const float*)d_in[11], (const float*)d_in[12],
        (const float*)d_in[13], (const float*)d_in[14],
        (const float*)d_in[15], (const float*)d_in[16],
        (const float*)d_in[17], (const float*)d_in[18]);

    const int nB = in_sizes[0] / 224;   // B = 131072
    hopfield_kernel<<<2048, 128>>>(sample, (float*)d_out, nB);
}

// round 12
// speedup vs baseline: 1.3767x; 1.1892x over previous
#include <cuda_runtime.h>

// ---------------------------------------------------------------------------
// M1_17008070492428: batched tiny Hopfield attention + classifier head.
//   B=131072 samples, each (S=14, D=16) -> (7,) softmax probs.
// R12 = R9 (best: 90.1us) + two latency cuts:
//   (a) cp.async (LDGSTS) double-buffered input prefetch: iteration i+1's
//       2 samples stream into the alternate smem buffer during iteration
//       i's compute; wait_group 1 arms the current buffer. Global-load
//       latency leaves the critical path.
//   (b) row-softmax max-shift removed (shift-invariant; scores provably
//       small, exp cannot overflow; the -1e30 key-pad mask still ->0).
// Pipeline: register-resident tf32 MMA QKV + S=QK^T (PI-permuted weights),
// r = wm/Z-weighted column sums of P, t = r@V on fragments, M stored
// PI-permuted so the final dot pairs correctly; shuffle reductions.
// ---------------------------------------------------------------------------

typedef unsigned int u32;
#define LN_EPS 1e-5f
#define FULLM 0xffffffffu

__device__ __forceinline__ u32 f2t(float x) {          // f32 bits as tf32
    return __float_as_uint(x);
}
__device__ __forceinline__ void cpasync16(void* smem, const void* gmem) {
    u32 s = (u32)__cvta_generic_to_shared(smem);
    asm volatile("cp.async.ca.shared.global [%0], [%1], 16;" :: "r"(s), "l"(gmem));
}
__device__ __forceinline__ void cp_commit() {
    asm volatile("cp.async.commit_group;");
}
__device__ __forceinline__ void cp_wait1() {
    asm volatile("cp.async.wait_group 1;");
}
__device__ __forceinline__ void mma8(float& d0, float& d1, float& d2, float& d3,
                                     u32 a0, u32 a1, u32 a2, u32 a3,
                                     u32 b0, u32 b1,
                                     float c0, float c1, float c2, float c3) {
    asm("mma.sync.aligned.m16n8k8.row.col.f32.tf32.tf32.f32 "
        "{%0,%1,%2,%3},{%4,%5,%6,%7},{%8,%9},{%10,%11,%12,%13};"
        : "=f"(d0), "=f"(d1), "=f"(d2), "=f"(d3)
        : "r"(a0), "r"(a1), "r"(a2), "r"(a3), "r"(b0), "r"(b1),
          "f"(c0), "f"(c1), "f"(c2), "f"(c3));
}

struct __align__(16) Params {
    float wq[16][16], wk[16][16], wv[16][16];  // PI-permuted rows, LN-gamma folded
    float bq[16], bk[16], bv[16];              // PI-permuted, LN-beta folded
    float M[7][16];                            // (Wb@Wo) with PI-permuted columns
    float ez[8];
    float wm[16];                              // Wm padded with zeros
};
__device__ Params g_P;

__global__ void setup_kernel(
    const float* __restrict__ lnqg, const float* __restrict__ lnqb,
    const float* __restrict__ lnkg, const float* __restrict__ lnkb,
    const float* __restrict__ lnvg, const float* __restrict__ lnvb,
    const float* __restrict__ Wq,  const float* __restrict__ bq,
    const float* __restrict__ Wk,  const float* __restrict__ bk,
    const float* __restrict__ Wv,  const float* __restrict__ bv,
    const float* __restrict__ Wo,  const float* __restrict__ bo,
    const float* __restrict__ Wm,  const float* __restrict__ bm,
    const float* __restrict__ Wb,  const float* __restrict__ bb)
{
    const int PI[16] = {0,4,1,5,2,6,3,7, 8,12,9,13,10,14,11,15};
    const int t = threadIdx.x;           // 256 threads, 1 block
    const int e = t >> 4, d = t & 15;
    const int pe = PI[e];
    g_P.wq[e][d] = Wq[pe * 16 + d] * lnqg[d];
    g_P.wk[e][d] = Wk[pe * 16 + d] * lnkg[d];
    g_P.wv[e][d] = Wv[pe * 16 + d] * lnvg[d];
    if (t < 16) {
        const int p = PI[t];
        float aq = bq[p], ak = bk[p], av = bv[p];
        #pragma unroll
        for (int i = 0; i < 16; i++) {
            aq = fmaf(lnqb[i], Wq[p * 16 + i], aq);
            ak = fmaf(lnkb[i], Wk[p * 16 + i], ak);
            av = fmaf(lnvb[i], Wv[p * 16 + i], av);
        }
        g_P.bq[t] = aq; g_P.bk[t] = ak; g_P.bv[t] = av;
        g_P.wm[t] = (t < 14) ? Wm[t] : 0.f;
    }
    if (t < 112) {
        const int c = t >> 4, dd = t & 15;
        const int pd = PI[dd];               // PI-permuted M columns
        float s = 0.f;
        for (int o = 0; o < 128; o++)
            s = fmaf(Wb[c * 128 + o], Wo[o * 16 + pd], s);
        g_P.M[c][dd] = s;
    }
    if (t >= 112 && t < 119) {
        const int c = t - 112;
        float c0 = 0.f;
        for (int s = 0; s < 14; s++) c0 += Wm[s];
        float z = bb[c];
        const float bmv = bm[0];
        for (int o = 0; o < 128; o++)
            z = fmaf(Wb[c * 128 + o], fmaf(c0, bo[o], bmv), z);
        g_P.ez[c] = z;
    }
    if (t == 119) g_P.ez[7] = 0.f;
}

__global__ __launch_bounds__(128, 4) void hopfield_kernel(
    const float* __restrict__ x, float* __restrict__ out, int nB)
{
    // [warp][buffer][sample][16 rows x 20 floats]  = 20 KB
    __shared__ __align__(16) float smT[4][2][2][16 * 20];
    const int tid  = threadIdx.x;
    const int lane = tid & 31;
    const int wid  = tid >> 5;
    const int fg   = lane >> 2;     // 0..7  (row group / B n-col)
    const int tg   = lane & 3;      // 0..3  (thread-in-quad)

    // ---- persistent weight B-fragments (raw f32 = truncated tf32) ----
    u32   bw[3][2][2][2];           // [proj][ntile][kstep][reg]
    float bs[3][2][2];
    {
        const float* Wp[3] = { &g_P.wq[0][0], &g_P.wk[0][0], &g_P.wv[0][0] };
        const float* Bp[3] = { g_P.bq, g_P.bk, g_P.bv };
        #pragma unroll
        for (int p = 0; p < 3; p++) {
            #pragma unroll
            for (int nt = 0; nt < 2; nt++) {
                #pragma unroll
                for (int ks = 0; ks < 2; ks++) {
                    const float* base = Wp[p] + (fg + 8 * nt) * 16 + 8 * ks;
                    bw[p][nt][ks][0] = f2t(__ldg(base + tg));
                    bw[p][nt][ks][1] = f2t(__ldg(base + tg + 4));
                }
                bs[p][nt][0] = __ldg(Bp[p] + 2 * tg + 8 * nt);
                bs[p][nt][1] = __ldg(Bp[p] + 2 * tg + 8 * nt + 1);
            }
        }
    }
    const float wmLo = g_P.wm[fg];
    const float wmHi = g_P.wm[fg + 8];      // 0 for rows 14,15
    float4 mz = make_float4(0.f, 0.f, 0.f, 0.f);
    float ezv = 0.f;
    if (fg < 7) {
        float2 a = *(const float2*)&g_P.M[fg][2 * tg];      // PI cols: pair with td
        float2 b = *(const float2*)&g_P.M[fg][8 + 2 * tg];
        mz = make_float4(a.x, a.y, b.x, b.y);
        ezv = g_P.ez[fg];
    }
    const int rsel = fg >> 1;        // realign shuffle source lane
    const bool rodd = (fg & 1);

    const int stride = gridDim.x * 4 * 2;

    // prefetch lambda: stream 2 samples at s0p into buffer b (always commits)
    auto prefetch = [&](int s0p, int b) {
        const float4* gp = (const float4*)(x + (long long)s0p * 224);
        #pragma unroll
        for (int j = 0; j < 4; j++) {
            const int i = lane + 32 * j;              // 0..127, need 0..111
            if (i < 112) {
                const int sm2 = (i >= 56);
                const int ii  = i - 56 * sm2;         // float4 idx within sample
                cpasync16(&smT[wid][b][sm2][(ii >> 2) * 20 + ((ii & 3) << 2)],
                          gp + i);
            }
        }
        cp_commit();
    };

    int s0 = (blockIdx.x * 4 + wid) * 2;
    if (s0 >= nB) return;
    prefetch(s0, 0);
    int buf = 0;

    for (; s0 < nB; s0 += stride) {
        const int nxt = s0 + stride;
        prefetch(nxt < nB ? nxt : 0, buf ^ 1);   // clamped: always commit
        cp_wait1();
        __syncwarp();

        #pragma unroll
        for (int smp = 0; smp < 2; smp++) {
            const int samp = s0 + smp;
            const float* Tile = smT[wid][buf][smp];

            // ---- gather x in fragment layout (bank-perfect LDS.32) ----
            float xlo[4], xhi[4];
            #pragma unroll
            for (int u = 0; u < 4; u++) {
                xlo[u] = Tile[fg * 20 + tg + 4 * u];
                xhi[u] = (fg < 6) ? Tile[(fg + 8) * 20 + tg + 4 * u] : 0.f;
            }
            // ---- LN via quad shuffles ----
            float s1l = ((xlo[0] + xlo[1]) + (xlo[2] + xlo[3]));
            float s2l = xlo[0] * xlo[0];
            s2l = fmaf(xlo[1], xlo[1], s2l); s2l = fmaf(xlo[2], xlo[2], s2l); s2l = fmaf(xlo[3], xlo[3], s2l);
            float s1h = ((xhi[0] + xhi[1]) + (xhi[2] + xhi[3]));
            float s2h = xhi[0] * xhi[0];
            s2h = fmaf(xhi[1], xhi[1], s2h); s2h = fmaf(xhi[2], xhi[2], s2h); s2h = fmaf(xhi[3], xhi[3], s2h);
            s1l += __shfl_xor_sync(FULLM, s1l, 1); s1l += __shfl_xor_sync(FULLM, s1l, 2);
            s2l += __shfl_xor_sync(FULLM, s2l, 1); s2l += __shfl_xor_sync(FULLM, s2l, 2);
            s1h += __shfl_xor_sync(FULLM, s1h, 1); s1h += __shfl_xor_sync(FULLM, s1h, 2);
            s2h += __shfl_xor_sync(FULLM, s2h, 1); s2h += __shfl_xor_sync(FULLM, s2h, 2);
            const float mL = s1l * 0.0625f;
            const float rL = rsqrtf(fmaf(-mL, mL, s2l * 0.0625f) + LN_EPS);
            const float mH = s1h * 0.0625f;
            const float rH = rsqrtf(fmaf(-mH, mH, s2h * 0.0625f) + LN_EPS);
            u32 a0 = f2t((xlo[0] - mL) * rL), a1 = f2t((xhi[0] - mH) * rH);
            u32 a2 = f2t((xlo[1] - mL) * rL), a3 = f2t((xhi[1] - mH) * rH);
            u32 a4 = f2t((xlo[2] - mL) * rL), a5 = f2t((xhi[2] - mH) * rH);
            u32 a6 = f2t((xlo[3] - mL) * rL), a7 = f2t((xhi[3] - mH) * rH);

            // ---- QKV (PI-permuted cols): D[:,e] = proj_true[:, PI[e]] ----
            float Q[8], K[8], V[8];
            #pragma unroll
            for (int p = 0; p < 3; p++) {
                float* D = (p == 0) ? Q : ((p == 1) ? K : V);
                #pragma unroll
                for (int nt = 0; nt < 2; nt++) {
                    float d0, d1, d2, d3;
                    mma8(d0, d1, d2, d3, a0, a1, a2, a3,
                         bw[p][nt][0][0], bw[p][nt][0][1],
                         bs[p][nt][0], bs[p][nt][1], bs[p][nt][0], bs[p][nt][1]);
                    mma8(d0, d1, d2, d3, a4, a5, a6, a7,
                         bw[p][nt][1][0], bw[p][nt][1][1], d0, d1, d2, d3);
                    D[nt * 4 + 0] = d0; D[nt * 4 + 1] = d1;
                    D[nt * 4 + 2] = d2; D[nt * 4 + 3] = d3;
                }
            }

            // ---- S = Q K^T : pure register MMA (cols = true keys) ----
            u32 qa0 = f2t(Q[0]), qa1 = f2t(Q[2]), qa2 = f2t(Q[1]), qa3 = f2t(Q[3]);
            u32 qa4 = f2t(Q[4]), qa5 = f2t(Q[6]), qa6 = f2t(Q[5]), qa7 = f2t(Q[7]);
            float t0, t1, t2, t3, u0, u1, u2, u3;
            mma8(t0, t1, t2, t3, qa0, qa1, qa2, qa3, f2t(K[0]), f2t(K[1]), 0.f, 0.f, 0.f, 0.f);
            mma8(t0, t1, t2, t3, qa4, qa5, qa6, qa7, f2t(K[4]), f2t(K[5]), t0, t1, t2, t3);
            mma8(u0, u1, u2, u3, qa0, qa1, qa2, qa3, f2t(K[2]), f2t(K[3]), 0.f, 0.f, 0.f, 0.f);
            mma8(u0, u1, u2, u3, qa4, qa5, qa6, qa7, f2t(K[6]), f2t(K[7]), u0, u1, u2, u3);
            if (tg == 3) { u0 = -1e30f; u1 = -1e30f; u2 = -1e30f; u3 = -1e30f; }  // keys 14,15

            // ---- softmax rows WITHOUT max-shift (scores are O(1)) ----
            float e0 = __expf(t0), e1 = __expf(t1), e4 = __expf(u0), e5 = __expf(u1);
            float e2 = __expf(t2), e3 = __expf(t3), e6 = __expf(u2), e7 = __expf(u3);
            float sl = (e0 + e1) + (e4 + e5);
            sl += __shfl_xor_sync(FULLM, sl, 1); sl += __shfl_xor_sync(FULLM, sl, 2);
            float sh = (e2 + e3) + (e6 + e7);
            sh += __shfl_xor_sync(FULLM, sh, 1); sh += __shfl_xor_sync(FULLM, sh, 2);
            const float wl = wmLo * __fdividef(1.f, sl);
            const float wh = wmHi * __fdividef(1.f, sh);

            // ---- r[key] = sum_q wP[q][key]  (reduce over fg) ----
            float rA = fmaf(e0, wl, e2 * wh);        // key = 2tg
            float rB = fmaf(e1, wl, e3 * wh);        // key = 2tg+1
            float rC = fmaf(e4, wl, e6 * wh);        // key = 8+2tg
            float rD = fmaf(e5, wl, e7 * wh);        // key = 8+2tg+1
            #pragma unroll
            for (int off = 4; off <= 16; off <<= 1) {
                rA += __shfl_xor_sync(FULLM, rA, off);
                rB += __shfl_xor_sync(FULLM, rB, off);
                rC += __shfl_xor_sync(FULLM, rC, off);
                rD += __shfl_xor_sync(FULLM, rD, off);
            }
            // realign: r_lo = r[fg], r_hi = r[fg+8]
            const float rAs = __shfl_sync(FULLM, rA, rsel);
            const float rBs = __shfl_sync(FULLM, rB, rsel);
            const float rCs = __shfl_sync(FULLM, rC, rsel);
            const float rDs = __shfl_sync(FULLM, rD, rsel);
            const float r_lo = rodd ? rBs : rAs;
            const float r_hi = rodd ? rDs : rCs;

            // ---- t over PI-cols: td0..td3 = t[PI[2tg]], t[PI[2tg+1]], ... ----
            float td0 = fmaf(r_lo, V[0], r_hi * V[2]);
            float td1 = fmaf(r_lo, V[1], r_hi * V[3]);
            float td2 = fmaf(r_lo, V[4], r_hi * V[6]);
            float td3 = fmaf(r_lo, V[5], r_hi * V[7]);
            #pragma unroll
            for (int off = 4; off <= 16; off <<= 1) {
                td0 += __shfl_xor_sync(FULLM, td0, off);
                td1 += __shfl_xor_sync(FULLM, td1, off);
                td2 += __shfl_xor_sync(FULLM, td2, off);
                td3 += __shfl_xor_sync(FULLM, td3, off);
            }

            // ---- z[c]: M stored PI-permuted, so mz pairs with td exactly ----
            float z = (fg < 7)
                ? fmaf(mz.x, td0, fmaf(mz.y, td1, fmaf(mz.z, td2, mz.w * td3)))
                : 0.f;
            z += __shfl_xor_sync(FULLM, z, 1);
            z += __shfl_xor_sync(FULLM, z, 2);
            // 7-class softmax without max-shift: |z| is O(1), no overflow risk
            float ex = (fg < 7) ? __expf(z + ezv) : 0.f;
            float se = ex;
            se += __shfl_xor_sync(FULLM, se, 4);
            se += __shfl_xor_sync(FULLM, se, 8);
            se += __shfl_xor_sync(FULLM, se, 16);
            if (tg == 0 && fg < 7)
                out[samp * 7 + fg] = __fdividef(ex, se);
        }
        buf ^= 1;
    }
}

extern "C" void kernel_launch(void* const* d_in, const int* in_sizes, int n_in,
                              void* d_out, int out_size)
{
    const float* sample = (const float*)d_in[0];
    setup_kernel<<<1, 256>>>(
        (const float*)d_in[1],  (const float*)d_in[2],
        (const float*)d_in[3],  (const float*)d_in[4],
        (const float*)d_in[5],  (const float*)d_in[6],
        (const float*)d_in[7],  (const float*)d_in[8],
        (const float*)d_in[9],  (const float*)d_in[10],
        (const float*)d_in[11], (const float*)d_in[12],
        (const float*)d_in[13], (const float*)d_in[14],
        (const float*)d_in[15], (const float*)d_in[16],
        (const float*)d_in[17], (const float*)d_in[18]);

    const int nB = in_sizes[0] / 224;   // B = 131072
    hopfield_kernel<<<2048, 128>>>(sample, (float*)d_out, nB);
}